// round 11
// baseline (speedup 1.0000x reference)
#include <cuda_runtime.h>
#include <math.h>
#include <stdint.h>

#define BQ    32
#define CIN   128
#define LIN   1024
#define NE    4
#define COUT  128
#define KW    64
#define LOUT  961          // 1024 - 64 + 1
#define NTILE 56
#define NTILES 18          // 18*56 = 1008 >= 961; 576 CTAs, 2/SM -> 1.95 waves
#define SWPAD 36           // W pair-row stride (words): LDSM rows on distinct banks
#define WNDW  120          // x window: NTILE + KW - 1 = 119, rounded up
#define NPAIR 32           // KW/2 f16x2 pairs per (o, c) row

// ---------------- scratch (device globals: no allocation allowed) ----------
__device__ float    g_gatex[BQ * CIN];
__device__ int      g_sel [BQ * 2];
__device__ float    g_selw[BQ * 2];
__device__ uint32_t g_w1h[NE * CIN * COUT * NPAIR];   // f16x2 W1, [e][c][o][p], 8.4MB

// ---------------- helpers -------------------------------------------------
__device__ __forceinline__ uint32_t pack_f16x2(float lo, float hi) {
    uint32_t r;
    asm("cvt.rn.f16x2.f32 %0, %1, %2;" : "=r"(r) : "f"(hi), "f"(lo));
    return r;
}

__device__ __forceinline__ uint32_t smem_u32(const void* p) {
    return (uint32_t)__cvta_generic_to_shared(p);
}

__device__ __forceinline__ void mma_f16(float* c,
                                        uint32_t a0, uint32_t a1, uint32_t a2, uint32_t a3,
                                        uint32_t b0, uint32_t b1) {
    asm volatile("mma.sync.aligned.m16n8k16.row.col.f32.f16.f16.f32 "
                 "{%0,%1,%2,%3}, {%4,%5,%6,%7}, {%8,%9}, {%0,%1,%2,%3};"
                 : "+f"(c[0]), "+f"(c[1]), "+f"(c[2]), "+f"(c[3])
                 : "r"(a0), "r"(a1), "r"(a2), "r"(a3), "r"(b0), "r"(b1));
}

// ---------------- kernel 0: W1 fp32 -> f16x2 pairs, [e][c][o][p] ----------
__global__ void k_wconv(const float* __restrict__ W1) {
    int w = blockIdx.x * 256 + threadIdx.x;   // [0, NE*CIN*COUT*NPAIR)
    int p = w & 31;
    int o = (w >> 5) & 127;
    int c = (w >> 12) & 127;
    int e = w >> 19;
    const float* src = W1 + (((size_t)(e * COUT + o) * CIN) + c) * KW + 2 * p;
    g_w1h[w] = pack_f16x2(src[0], src[1]);
}

// ---------------- kernel 1: gate_x = mean over L (warp per row) -----------
__global__ void k_gatex(const float* __restrict__ x) {
    int row  = blockIdx.x * 4 + (threadIdx.x >> 5);   // (b, c) flattened
    int lane = threadIdx.x & 31;
    const float4* xp = (const float4*)(x + (size_t)row * LIN);
    float s = 0.f;
#pragma unroll
    for (int k = 0; k < 8; ++k) {
        float4 v = xp[lane + k * 32];
        s += (v.x + v.y) + (v.z + v.w);
    }
#pragma unroll
    for (int off = 16; off; off >>= 1) s += __shfl_down_sync(0xffffffffu, s, off);
    if (lane == 0) g_gatex[row] = s * (1.0f / (float)LIN);
}

// ---------------- kernel 2: gating, top-k, loss ---------------------------
__device__ __forceinline__ float cv_sq4(const float* w) {
    float mn = 0.25f * (w[0] + w[1] + w[2] + w[3]);
    float s = 0.f;
#pragma unroll
    for (int e = 0; e < 4; ++e) { float d = w[e] - mn; s += d * d; }
    s *= (1.0f / 3.0f);                    // ddof = 1
    return s / (mn * mn + 1e-10f);
}

__global__ void k_gate(const float* __restrict__ noise,
                       const float* __restrict__ w_gate,
                       const float* __restrict__ w_noise,
                       float* __restrict__ out, int loss_idx)
{
    int b = threadIdx.x;                   // 32 threads, one per batch row
    float clean[NE] = {0.f, 0.f, 0.f, 0.f};
    float raw[NE]   = {0.f, 0.f, 0.f, 0.f};
    for (int c = 0; c < CIN; ++c) {
        float gx = g_gatex[b * CIN + c];
#pragma unroll
        for (int e = 0; e < NE; ++e) {
            clean[e] = fmaf(gx, w_gate[c * NE + e],  clean[e]);
            raw[e]   = fmaf(gx, w_noise[c * NE + e], raw[e]);
        }
    }
    float nstd[NE], noisy[NE], sm[NE];
    float m = -1e30f;
#pragma unroll
    for (int e = 0; e < NE; ++e) {
        float r  = raw[e];
        float sp = (r > 20.f) ? r : log1pf(expf(r));   // softplus
        nstd[e]  = sp + 0.01f;                          // NOISE_EPS
        noisy[e] = clean[e] + noise[b * NE + e] * nstd[e];
        m = fmaxf(m, noisy[e]);
    }
    float ssum = 0.f;
#pragma unroll
    for (int e = 0; e < NE; ++e) { sm[e] = expf(noisy[e] - m); ssum += sm[e]; }
    float inv = 1.f / ssum;
#pragma unroll
    for (int e = 0; e < NE; ++e) sm[e] *= inv;

    int   idx[4] = {0, 1, 2, 3};
    float v[4]   = {sm[0], sm[1], sm[2], sm[3]};
#pragma unroll
    for (int a = 0; a < 3; ++a)
#pragma unroll
        for (int q = a + 1; q < 4; ++q)
            if (v[q] > v[a]) {
                float tv = v[a]; v[a] = v[q]; v[q] = tv;
                int   ti = idx[a]; idx[a] = idx[q]; idx[q] = ti;
            }

    float e1 = expf(v[1] - v[0]);
    float gs = 1.f + e1;
    float g0 = 1.f / gs;
    float g1 = e1 / gs;
    g_sel [b * 2 + 0] = idx[0];  g_sel [b * 2 + 1] = idx[1];
    g_selw[b * 2 + 0] = g0;      g_selw[b * 2 + 1] = g1;

    float gates[4] = {0.f, 0.f, 0.f, 0.f};
    gates[idx[0]] = g0;
    gates[idx[1]] = g1;

    float thr_in  = v[2];
    float thr_out = v[1];
    float loadc[4];
#pragma unroll
    for (int e = 0; e < NE; ++e) {
        bool  is_in = noisy[e] > thr_in;
        float thr   = is_in ? thr_in : thr_out;
        float z     = (clean[e] - thr) / nstd[e];
        loadc[e]    = 0.5f * (1.f + erff(z * 0.70710678118654752f));
    }

    float imp[4], ld[4];
#pragma unroll
    for (int e = 0; e < NE; ++e) {
        float a = gates[e], l2 = loadc[e];
        for (int off = 16; off; off >>= 1) {
            a  += __shfl_down_sync(0xffffffffu, a,  off);
            l2 += __shfl_down_sync(0xffffffffu, l2, off);
        }
        imp[e] = a; ld[e] = l2;
    }
    if (b == 0)
        out[loss_idx] = 0.01f * (cv_sq4(imp) + cv_sq4(ld));
}

// ---------------- kernel 3: fp16 tensor-core sparse conv experts ----------
// grid: (NTILES=18, BQ=32) = 576 CTAs, 256 threads (8 warps), 2 CTAs/SM.
// CTA tile: M=128 (Cout) x N=56 (l). Warp w owns m-rows [w*16, +16) and the
// FULL N=56 (no n-half duplication -> A-LDSM per CTA halves).
// 2 resident CTAs ping-pong: one CTA's barrier/staging bubble is covered by
// the other CTA's MMA bursts (R10 showed tensor pipe 60% with 1 CTA — the
// idle 40% is latency-hiding deficit, not barrier count).
// R9 single-buffer structure, ldmatrix.x4 A-frags, W pre-converted f16x2.
__global__ void __launch_bounds__(256, 2)
k_conv(const float* __restrict__ x,
       const float* __restrict__ b1,
       const float* __restrict__ W2,
       const float* __restrict__ b2,
       float* __restrict__ out)
{
    __shared__ __align__(16) uint32_t sw[COUT * SWPAD]; // f16x2 tap pairs, 18.4KB
    __shared__ uint32_t sxp[WNDW];                      // paired x window f16x2
    __shared__ float sred[8][4][28];                    // epilogue partials
    __shared__ float sz[2][NTILE];
    __shared__ float ysum[2][NTILE];
    __shared__ float sW2[2][COUT];
    __shared__ float sb1[COUT];

    const int b    = blockIdx.y;
    const int l0   = blockIdx.x * NTILE;
    const int tid  = threadIdx.x;
    const int warp = tid >> 5;          // 0..7 = m-group
    const int lane = tid & 31;
    const int g    = lane >> 2;
    const int t4   = lane & 3;
    const int m0   = warp * 16;
    const int rlo  = m0 + g;
    const int rhi  = m0 + g + 8;
    const int so   = tid >> 4;          // W staging: o base (o = so + r*16)
    const int sq   = tid & 15;          // W staging: pair duo [2sq, 2sq+2)

    // ldmatrix per-lane base: row m0+(lane&15), word (lane>>4)*4; +kk*32B
    const uint32_t a_base =
        smem_u32(&sw[(m0 + (lane & 15)) * SWPAD + ((lane >> 4) << 2)]);

    const float* xb = x + (size_t)b * CIN * LIN;
    const bool xact = (tid < WNDW);

    if (tid < 2 * NTILE) {
        int t = tid >= NTILE;
        ysum[t][tid - t * NTILE] = 0.f;
    }

    for (int slot = 0; slot < 2; ++slot) {
        const int   e  = g_sel [b * 2 + slot];
        const float gw = g_selw[b * 2 + slot];
        const uint32_t* Whe = g_w1h + (size_t)e * (CIN * COUT * NPAIR);

        sW2[tid >> 7][tid & 127] = W2[e * 2 * COUT + tid];   // 256 == 2*COUT
        if (tid < COUT) sb1[tid] = b1[e * COUT + tid];

        float acc[7][4];
#pragma unroll
        for (int i = 0; i < 7; ++i)
#pragma unroll
            for (int j = 0; j < 4; ++j) acc[i][j] = 0.f;

        // ---- prefetch channel 0 (f16x2 pairs) ----
        uint2 wreg[8];
        float xra = 0.f, xrb = 0.f;
#pragma unroll
        for (int r = 0; r < 8; ++r) {
            int o = so + r * 16;
            wreg[r] = *(const uint2*)(Whe + (size_t)o * NPAIR + 2 * sq);
        }
        if (xact) {
            int l = l0 + tid;
            xra = (l < LIN)     ? xb[l]     : 0.f;
            xrb = (l + 1 < LIN) ? xb[l + 1] : 0.f;   // same L1 line
        }

        for (int c = 0; c < CIN; ++c) {
            __syncthreads();            // prior compute done reading sw/sxp
            // stage channel c (already f16x2 — straight STS.64)
#pragma unroll
            for (int r = 0; r < 8; ++r) {
                int o = so + r * 16;
                *(uint2*)&sw[o * SWPAD + sq * 2] = wreg[r];
            }
            if (xact) sxp[tid] = pack_f16x2(xra, xrb);
            __syncthreads();            // staging visible

            // prefetch channel c+1 (hidden under the MMAs below)
            if (c + 1 < CIN) {
                const uint32_t* Whc = Whe + (size_t)(c + 1) * (COUT * NPAIR);
                const float*    xc  = xb + (size_t)(c + 1) * LIN;
#pragma unroll
                for (int r = 0; r < 8; ++r) {
                    int o = so + r * 16;
                    wreg[r] = *(const uint2*)(Whc + (size_t)o * NPAIR + 2 * sq);
                }
                if (xact) {
                    int l = l0 + tid;
                    xra = (l < LIN)     ? xc[l]     : 0.f;
                    xrb = (l + 1 < LIN) ? xc[l + 1] : 0.f;
                }
            }

            // B pairs: P[j] = sxp[bbase + 8j], one LDS.32 each.
            uint32_t P[14];
            const int bbase = g + 2 * t4;
#pragma unroll
            for (int j = 0; j < 14; ++j) P[j] = sxp[bbase + 8 * j];

#pragma unroll
            for (int kk = 0; kk < 4; ++kk) {
                uint32_t a0, a1, a2, a3;
                asm volatile(
                    "ldmatrix.sync.aligned.m8n8.x4.shared.b16 {%0,%1,%2,%3}, [%4];"
                    : "=r"(a0), "=r"(a1), "=r"(a2), "=r"(a3)
                    : "r"(a_base + kk * 32));
#pragma unroll
                for (int nb = 0; nb < 7; ++nb) {
                    int s = 2 * kk + nb;
                    mma_f16(acc[nb], a0, a1, a2, a3, P[s], P[s + 1]);
                }
            }
        }

        // ---- epilogue: bias + relu + W2 partials, reduce over Cout ----
        float b1lo = sb1[rlo], b1hi = sb1[rhi];
        float w2lo0 = sW2[0][rlo], w2hi0 = sW2[0][rhi];
        float w2lo1 = sW2[1][rlo], w2hi1 = sW2[1][rhi];
        float p[28];                    // [nb*4 + r*2 + t], r = col parity
#pragma unroll
        for (int nb = 0; nb < 7; ++nb) {
            float h00 = fmaxf(acc[nb][0] + b1lo, 0.f);   // (rlo, col even)
            float h01 = fmaxf(acc[nb][1] + b1lo, 0.f);   // (rlo, col odd)
            float h10 = fmaxf(acc[nb][2] + b1hi, 0.f);   // (rhi, col even)
            float h11 = fmaxf(acc[nb][3] + b1hi, 0.f);   // (rhi, col odd)
            p[nb * 4 + 0] = fmaf(w2lo0, h00, w2hi0 * h10);
            p[nb * 4 + 1] = fmaf(w2lo1, h00, w2hi1 * h10);
            p[nb * 4 + 2] = fmaf(w2lo0, h01, w2hi0 * h11);
            p[nb * 4 + 3] = fmaf(w2lo1, h01, w2hi1 * h11);
        }
        // reduce over g (8 lanes sharing t4)
#pragma unroll
        for (int j = 0; j < 28; ++j) {
            p[j] += __shfl_down_sync(0xffffffffu, p[j], 16);
            p[j] += __shfl_down_sync(0xffffffffu, p[j], 8);
            p[j] += __shfl_down_sync(0xffffffffu, p[j], 4);
        }
        __syncthreads();                // sred free from prior use
        if (lane < 4) {
#pragma unroll
            for (int j = 0; j < 28; ++j) sred[warp][lane][j] = p[j];
        }
        __syncthreads();

        // z[t][col]: sum the 8 m-warps
        if (tid < 2 * NTILE) {
            int t   = tid >= NTILE;
            int col = tid - t * NTILE;
            int nb  = col >> 3;
            int tt4 = (col >> 1) & 3;
            int r   = col & 1;
            int pj  = nb * 4 + r * 2 + t;
            float z = b2[e * 2 + t];
#pragma unroll
            for (int w8 = 0; w8 < 8; ++w8) z += sred[w8][tt4][pj];
            sz[t][col] = z;
        }
        __syncthreads();

        // 2-way softmax over t, gate-weighted accumulate
        if (tid < NTILE) {
            float z0 = sz[0][tid], z1 = sz[1][tid];
            float mm = fmaxf(z0, z1);
            float a0 = expf(z0 - mm), a1 = expf(z1 - mm);
            float is = 1.f / (a0 + a1);
            ysum[0][tid] += gw * a0 * is;
            ysum[1][tid] += gw * a1 * is;
        }
        __syncthreads();
    }

    if (tid < 2 * NTILE) {
        int t = tid >= NTILE, l = tid - t * NTILE;
        int gl = l0 + l;
        if (gl < LOUT)
            out[((size_t)b * 2 + t) * LOUT + gl] = ysum[t][l];
    }
}

// ---------------- launcher ------------------------------------------------
extern "C" void kernel_launch(void* const* d_in, const int* in_sizes, int n_in,
                              void* d_out, int out_size)
{
    const float* x       = (const float*)d_in[0];
    const float* noise   = (const float*)d_in[1];
    const float* w_gate  = (const float*)d_in[2];
    const float* w_noise = (const float*)d_in[3];
    const float* W1      = (const float*)d_in[4];
    const float* b1      = (const float*)d_in[5];
    const float* W2      = (const float*)d_in[6];
    const float* b2      = (const float*)d_in[7];
    float* out = (float*)d_out;

    k_wconv<<<NE * CIN * COUT * NPAIR / 256, 256>>>(W1);
    k_gatex<<<BQ * CIN / 4, 128>>>(x);
    k_gate<<<1, 32>>>(noise, w_gate, w_noise, out, out_size - 1);
    dim3 grid(NTILES, BQ);
    k_conv<<<grid, 256>>>(x, b1, W2, b2, out);
}

// round 13
// speedup vs baseline: 1.2365x; 1.2365x over previous
#include <cuda_runtime.h>
#include <math.h>
#include <stdint.h>

#define BQ    32
#define CIN   128
#define LIN   1024
#define NE    4
#define COUT  128
#define KW    64
#define LOUT  961          // 1024 - 64 + 1
#define NTILE 56
#define NTILES 18          // 18*56 = 1008 >= 961; 576 CTAs, 2/SM -> 1.95 waves
#define WNDW  120          // x window: NTILE + KW - 1 = 119, rounded up
// pre-swizzled A fragments: [e][c][warp(8)][kk(4)][lane(32)][q(4)] uint32
#define ACH   (8 * 4 * 32 * 4)          // words per (e,c) = 4096 (16KB)

// ---------------- scratch (device globals: no allocation allowed) ----------
__device__ float    g_gatex[BQ * CIN];
__device__ int      g_sel [BQ * 2];
__device__ float    g_selw[BQ * 2];
__device__ uint32_t g_w1h[NE * CIN * ACH];   // fragment-ordered f16x2 W1, 8.4MB

// ---------------- helpers -------------------------------------------------
__device__ __forceinline__ uint32_t pack_f16x2(float lo, float hi) {
    uint32_t r;
    asm("cvt.rn.f16x2.f32 %0, %1, %2;" : "=r"(r) : "f"(hi), "f"(lo));
    return r;
}

__device__ __forceinline__ void mma_f16(float* c,
                                        uint32_t a0, uint32_t a1, uint32_t a2, uint32_t a3,
                                        uint32_t b0, uint32_t b1) {
    asm volatile("mma.sync.aligned.m16n8k16.row.col.f32.f16.f16.f32 "
                 "{%0,%1,%2,%3}, {%4,%5,%6,%7}, {%8,%9}, {%0,%1,%2,%3};"
                 : "+f"(c[0]), "+f"(c[1]), "+f"(c[2]), "+f"(c[3])
                 : "r"(a0), "r"(a1), "r"(a2), "r"(a3), "r"(b0), "r"(b1));
}

// One channel's 28 MMAs: A fragments (4 x uint4, register-direct) against
// the 14 B pairs read from the shared x window. All indices compile-time
// constant after inlining.
__device__ __forceinline__ void mma_channel(float acc[7][4],
                                            uint4 A0, uint4 A1, uint4 A2, uint4 A3,
                                            const uint32_t* __restrict__ sxp,
                                            int bb)
{
    uint32_t P[14];
#pragma unroll
    for (int j = 0; j < 14; ++j) P[j] = sxp[bb + 8 * j];
#pragma unroll
    for (int nb = 0; nb < 7; ++nb)
        mma_f16(acc[nb], A0.x, A0.y, A0.z, A0.w, P[nb],     P[nb + 1]);
#pragma unroll
    for (int nb = 0; nb < 7; ++nb)
        mma_f16(acc[nb], A1.x, A1.y, A1.z, A1.w, P[nb + 2], P[nb + 3]);
#pragma unroll
    for (int nb = 0; nb < 7; ++nb)
        mma_f16(acc[nb], A2.x, A2.y, A2.z, A2.w, P[nb + 4], P[nb + 5]);
#pragma unroll
    for (int nb = 0; nb < 7; ++nb)
        mma_f16(acc[nb], A3.x, A3.y, A3.z, A3.w, P[nb + 6], P[nb + 7]);
}

// ---------------- kernel 0: W1 fp32 -> per-lane A fragments ---------------
// Output word idx: ((((e*CIN + c)*8 + wp)*4 + kk)*32 + lane)*4 + q
// Thread computes one uint4 (q=0..3):
//   a0 = W[o=wp*16+g]  taps (16kk+2t4, +1)     a1 = same taps, o+8
//   a2 = W[o=wp*16+g]  taps (16kk+8+2t4, +1)   a3 = same taps, o+8
__global__ void k_wconv(const float* __restrict__ W1) {
    int idx  = blockIdx.x * 256 + threadIdx.x;    // [0, NE*CIN*8*4*32)
    int lane = idx & 31;
    int kk   = (idx >> 5) & 3;
    int wp   = (idx >> 7) & 7;
    int c    = (idx >> 10) & 127;
    int e    = idx >> 17;
    int g    = lane >> 2;
    int t4   = lane & 3;
    int olo  = wp * 16 + g;
    int ohi  = olo + 8;
    int tap0 = kk * 16 + 2 * t4;
    const float* Wlo = W1 + ((size_t)(e * COUT + olo) * CIN + c) * KW;
    const float* Whi = W1 + ((size_t)(e * COUT + ohi) * CIN + c) * KW;
    uint4 u;
    u.x = pack_f16x2(Wlo[tap0],     Wlo[tap0 + 1]);
    u.y = pack_f16x2(Whi[tap0],     Whi[tap0 + 1]);
    u.z = pack_f16x2(Wlo[tap0 + 8], Wlo[tap0 + 9]);
    u.w = pack_f16x2(Whi[tap0 + 8], Whi[tap0 + 9]);
    *(uint4*)(g_w1h + (size_t)idx * 4) = u;
}

// ---------------- kernel 1: gate_x = mean over L (warp per row) -----------
__global__ void k_gatex(const float* __restrict__ x) {
    int row  = blockIdx.x * 4 + (threadIdx.x >> 5);   // (b, c) flattened
    int lane = threadIdx.x & 31;
    const float4* xp = (const float4*)(x + (size_t)row * LIN);
    float s = 0.f;
#pragma unroll
    for (int k = 0; k < 8; ++k) {
        float4 v = xp[lane + k * 32];
        s += (v.x + v.y) + (v.z + v.w);
    }
#pragma unroll
    for (int off = 16; off; off >>= 1) s += __shfl_down_sync(0xffffffffu, s, off);
    if (lane == 0) g_gatex[row] = s * (1.0f / (float)LIN);
}

// ---------------- kernel 2: gating, top-k, loss ---------------------------
__device__ __forceinline__ float cv_sq4(const float* w) {
    float mn = 0.25f * (w[0] + w[1] + w[2] + w[3]);
    float s = 0.f;
#pragma unroll
    for (int e = 0; e < 4; ++e) { float d = w[e] - mn; s += d * d; }
    s *= (1.0f / 3.0f);                    // ddof = 1
    return s / (mn * mn + 1e-10f);
}

__global__ void k_gate(const float* __restrict__ noise,
                       const float* __restrict__ w_gate,
                       const float* __restrict__ w_noise,
                       float* __restrict__ out, int loss_idx)
{
    int b = threadIdx.x;                   // 32 threads, one per batch row
    float clean[NE] = {0.f, 0.f, 0.f, 0.f};
    float raw[NE]   = {0.f, 0.f, 0.f, 0.f};
    for (int c = 0; c < CIN; ++c) {
        float gx = g_gatex[b * CIN + c];
#pragma unroll
        for (int e = 0; e < NE; ++e) {
            clean[e] = fmaf(gx, w_gate[c * NE + e],  clean[e]);
            raw[e]   = fmaf(gx, w_noise[c * NE + e], raw[e]);
        }
    }
    float nstd[NE], noisy[NE], sm[NE];
    float m = -1e30f;
#pragma unroll
    for (int e = 0; e < NE; ++e) {
        float r  = raw[e];
        float sp = (r > 20.f) ? r : log1pf(expf(r));   // softplus
        nstd[e]  = sp + 0.01f;                          // NOISE_EPS
        noisy[e] = clean[e] + noise[b * NE + e] * nstd[e];
        m = fmaxf(m, noisy[e]);
    }
    float ssum = 0.f;
#pragma unroll
    for (int e = 0; e < NE; ++e) { sm[e] = expf(noisy[e] - m); ssum += sm[e]; }
    float inv = 1.f / ssum;
#pragma unroll
    for (int e = 0; e < NE; ++e) sm[e] *= inv;

    int   idx[4] = {0, 1, 2, 3};
    float v[4]   = {sm[0], sm[1], sm[2], sm[3]};
#pragma unroll
    for (int a = 0; a < 3; ++a)
#pragma unroll
        for (int q = a + 1; q < 4; ++q)
            if (v[q] > v[a]) {
                float tv = v[a]; v[a] = v[q]; v[q] = tv;
                int   ti = idx[a]; idx[a] = idx[q]; idx[q] = ti;
            }

    float e1 = expf(v[1] - v[0]);
    float gs = 1.f + e1;
    float g0 = 1.f / gs;
    float g1 = e1 / gs;
    g_sel [b * 2 + 0] = idx[0];  g_sel [b * 2 + 1] = idx[1];
    g_selw[b * 2 + 0] = g0;      g_selw[b * 2 + 1] = g1;

    float gates[4] = {0.f, 0.f, 0.f, 0.f};
    gates[idx[0]] = g0;
    gates[idx[1]] = g1;

    float thr_in  = v[2];
    float thr_out = v[1];
    float loadc[4];
#pragma unroll
    for (int e = 0; e < NE; ++e) {
        bool  is_in = noisy[e] > thr_in;
        float thr   = is_in ? thr_in : thr_out;
        float z     = (clean[e] - thr) / nstd[e];
        loadc[e]    = 0.5f * (1.f + erff(z * 0.70710678118654752f));
    }

    float imp[4], ld[4];
#pragma unroll
    for (int e = 0; e < NE; ++e) {
        float a = gates[e], l2 = loadc[e];
        for (int off = 16; off; off >>= 1) {
            a  += __shfl_down_sync(0xffffffffu, a,  off);
            l2 += __shfl_down_sync(0xffffffffu, l2, off);
        }
        imp[e] = a; ld[e] = l2;
    }
    if (b == 0)
        out[loss_idx] = 0.01f * (cv_sq4(imp) + cv_sq4(ld));
}

// ---------------- kernel 3: fp16 tensor-core sparse conv experts ----------
// grid: (NTILES=18, BQ=32) = 576 CTAs, 256 threads (8 warps), 2 CTAs/SM.
// CTA tile: M=128 (Cout) x N=56 (l). Warp w owns m-rows [w*16,+16), full N.
// A operand REGISTER-DIRECT from pre-swizzled g_w1h: 4 coalesced LDG.128 per
// thread per channel — no W STS/LDSM (R11 ncu: L1 68% co-critical with
// tensor 58%; W smem round-trip was 2/3 of L1 traffic). Barriers now order
// only the 480B x-window. Channel loop unrolled x2, named register sets.
__global__ void __launch_bounds__(256, 2)
k_conv(const float* __restrict__ x,
       const float* __restrict__ b1,
       const float* __restrict__ W2,
       const float* __restrict__ b2,
       float* __restrict__ out)
{
    __shared__ uint32_t sxp[WNDW];      // paired x window f16x2
    __shared__ float sred[8][4][28];    // epilogue partials
    __shared__ float sz[2][NTILE];
    __shared__ float ysum[2][NTILE];
    __shared__ float sW2[2][COUT];
    __shared__ float sb1[COUT];

    const int b    = blockIdx.y;
    const int l0   = blockIdx.x * NTILE;
    const int tid  = threadIdx.x;
    const int warp = tid >> 5;          // 0..7 = m-group
    const int lane = tid & 31;
    const int g    = lane >> 2;
    const int t4   = lane & 3;
    const int m0   = warp * 16;
    const int rlo  = m0 + g;
    const int rhi  = m0 + g + 8;

    const float* xb = x + (size_t)b * CIN * LIN;
    const bool xact = (tid < WNDW);
    const int  xl   = l0 + tid;
    const int  bb   = g + 2 * t4;

    if (tid < 2 * NTILE) {
        int t = tid >= NTILE;
        ysum[t][tid - t * NTILE] = 0.f;
    }

    // per-thread A-fragment offset within one (e,c) block: warp/kk/lane
    const size_t a_toff = (((size_t)warp * 4) * 32 + lane) * 4;  // + kk*128

    for (int slot = 0; slot < 2; ++slot) {
        const int   e  = g_sel [b * 2 + slot];
        const float gw = g_selw[b * 2 + slot];
        const uint32_t* Ae = g_w1h + (size_t)e * (CIN * ACH) + a_toff;

        sW2[tid >> 7][tid & 127] = W2[e * 2 * COUT + tid];   // 256 == 2*COUT
        if (tid < COUT) sb1[tid] = b1[e * COUT + tid];

        float acc[7][4];
#pragma unroll
        for (int i = 0; i < 7; ++i)
#pragma unroll
            for (int j = 0; j < 4; ++j) acc[i][j] = 0.f;

        // A fragment double registers (named) + x staging regs
        uint4 A_0, A_1, A_2, A_3, B_0, B_1, B_2, B_3;
        float xraA = 0.f, xrbA = 0.f, xraB = 0.f, xrbB = 0.f;

        // ---- preload channel 0 into set A ----
        A_0 = *(const uint4*)(Ae + 0 * 128);
        A_1 = *(const uint4*)(Ae + 1 * 128);
        A_2 = *(const uint4*)(Ae + 2 * 128);
        A_3 = *(const uint4*)(Ae + 3 * 128);
        if (xact) {
            xraA = (xl < LIN)     ? xb[xl]     : 0.f;
            xrbA = (xl + 1 < LIN) ? xb[xl + 1] : 0.f;
        }

        for (int c = 0; c < CIN; c += 2) {
            // ---- even channel c: stage xA; prefetch c+1 into set B ----
            __syncthreads();            // prior channel's P reads done
            if (xact) sxp[tid] = pack_f16x2(xraA, xrbA);
            __syncthreads();
            {
                const uint32_t* An = Ae + (size_t)(c + 1) * ACH;
                const float*    xc = xb + (size_t)(c + 1) * LIN;
                B_0 = *(const uint4*)(An + 0 * 128);
                B_1 = *(const uint4*)(An + 1 * 128);
                B_2 = *(const uint4*)(An + 2 * 128);
                B_3 = *(const uint4*)(An + 3 * 128);
                if (xact) {
                    xraB = (xl < LIN)     ? xc[xl]     : 0.f;
                    xrbB = (xl + 1 < LIN) ? xc[xl + 1] : 0.f;
                }
            }
            mma_channel(acc, A_0, A_1, A_2, A_3, sxp, bb);

            // ---- odd channel c+1: stage xB; prefetch c+2 into set A ----
            __syncthreads();
            if (xact) sxp[tid] = pack_f16x2(xraB, xrbB);
            __syncthreads();
            if (c + 2 < CIN) {
                const uint32_t* An = Ae + (size_t)(c + 2) * ACH;
                const float*    xc = xb + (size_t)(c + 2) * LIN;
                A_0 = *(const uint4*)(An + 0 * 128);
                A_1 = *(const uint4*)(An + 1 * 128);
                A_2 = *(const uint4*)(An + 2 * 128);
                A_3 = *(const uint4*)(An + 3 * 128);
                if (xact) {
                    xraA = (xl < LIN)     ? xc[xl]     : 0.f;
                    xrbA = (xl + 1 < LIN) ? xc[xl + 1] : 0.f;
                }
            }
            mma_channel(acc, B_0, B_1, B_2, B_3, sxp, bb);
        }

        // ---- epilogue: bias + relu + W2 partials, reduce over Cout ----
        float b1lo = sb1[rlo], b1hi = sb1[rhi];
        float w2lo0 = sW2[0][rlo], w2hi0 = sW2[0][rhi];
        float w2lo1 = sW2[1][rlo], w2hi1 = sW2[1][rhi];
        float p[28];                    // [nb*4 + r*2 + t], r = col parity
#pragma unroll
        for (int nb = 0; nb < 7; ++nb) {
            float h00 = fmaxf(acc[nb][0] + b1lo, 0.f);   // (rlo, col even)
            float h01 = fmaxf(acc[nb][1] + b1lo, 0.f);   // (rlo, col odd)
            float h10 = fmaxf(acc[nb][2] + b1hi, 0.f);   // (rhi, col even)
            float h11 = fmaxf(acc[nb][3] + b1hi, 0.f);   // (rhi, col odd)
            p[nb * 4 + 0] = fmaf(w2lo0, h00, w2hi0 * h10);
            p[nb * 4 + 1] = fmaf(w2lo1, h00, w2hi1 * h10);
            p[nb * 4 + 2] = fmaf(w2lo0, h01, w2hi0 * h11);
            p[nb * 4 + 3] = fmaf(w2lo1, h01, w2hi1 * h11);
        }
        // reduce over g (8 lanes sharing t4)
#pragma unroll
        for (int j = 0; j < 28; ++j) {
            p[j] += __shfl_down_sync(0xffffffffu, p[j], 16);
            p[j] += __shfl_down_sync(0xffffffffu, p[j], 8);
            p[j] += __shfl_down_sync(0xffffffffu, p[j], 4);
        }
        __syncthreads();                // sred free from prior use
        if (lane < 4) {
#pragma unroll
            for (int j = 0; j < 28; ++j) sred[warp][lane][j] = p[j];
        }
        __syncthreads();

        // z[t][col]: sum the 8 m-warps
        if (tid < 2 * NTILE) {
            int t   = tid >= NTILE;
            int col = tid - t * NTILE;
            int nb  = col >> 3;
            int tt4 = (col >> 1) & 3;
            int r   = col & 1;
            int pj  = nb * 4 + r * 2 + t;
            float z = b2[e * 2 + t];
#pragma unroll
            for (int w8 = 0; w8 < 8; ++w8) z += sred[w8][tt4][pj];
            sz[t][col] = z;
        }
        __syncthreads();

        // 2-way softmax over t, gate-weighted accumulate
        if (tid < NTILE) {
            float z0 = sz[0][tid], z1 = sz[1][tid];
            float mm = fmaxf(z0, z1);
            float a0 = expf(z0 - mm), a1 = expf(z1 - mm);
            float is = 1.f / (a0 + a1);
            ysum[0][tid] += gw * a0 * is;
            ysum[1][tid] += gw * a1 * is;
        }
        __syncthreads();
    }

    if (tid < 2 * NTILE) {
        int t = tid >= NTILE, l = tid - t * NTILE;
        int gl = l0 + l;
        if (gl < LOUT)
            out[((size_t)b * 2 + t) * LOUT + gl] = ysum[t][l];
    }
}

// ---------------- launcher ------------------------------------------------
extern "C" void kernel_launch(void* const* d_in, const int* in_sizes, int n_in,
                              void* d_out, int out_size)
{
    const float* x       = (const float*)d_in[0];
    const float* noise   = (const float*)d_in[1];
    const float* w_gate  = (const float*)d_in[2];
    const float* w_noise = (const float*)d_in[3];
    const float* W1      = (const float*)d_in[4];
    const float* b1      = (const float*)d_in[5];
    const float* W2      = (const float*)d_in[6];
    const float* b2      = (const float*)d_in[7];
    float* out = (float*)d_out;

    k_wconv<<<NE * CIN * 8 * 4 * 32 / 256, 256>>>(W1);
    k_gatex<<<BQ * CIN / 4, 128>>>(x);
    k_gate<<<1, 32>>>(noise, w_gate, w_noise, out, out_size - 1);
    dim3 grid(NTILES, BQ);
    k_conv<<<grid, 256>>>(x, b1, W2, b2, out);
}

// round 14
// speedup vs baseline: 1.3484x; 1.0905x over previous
#include <cuda_runtime.h>
#include <math.h>
#include <stdint.h>

#define BQ    32
#define CIN   128
#define LIN   1024
#define NE    4
#define COUT  128
#define KW    64
#define LOUT  961          // 1024 - 64 + 1
#define NTILE 56
#define NTILES 18          // 18*56 = 1008 >= 961; 576 CTAs, 2/SM -> 1.95 waves
#define WNDW  120          // x window: NTILE + KW - 1 = 119, rounded up
// pre-swizzled A fragments: [e][c][warp(8)][kk(4)][lane(32)][q(4)] uint32
#define ACH   (8 * 4 * 32 * 4)          // words per (e,c) = 4096 (16KB)

// ---------------- scratch (device globals: no allocation allowed) ----------
__device__ float    g_gatex[BQ * CIN];
__device__ int      g_sel [BQ * 2];
__device__ float    g_selw[BQ * 2];
__device__ uint32_t g_w1h[NE * CIN * ACH];   // fragment-ordered f16x2 W1, 8.4MB

// ---------------- helpers -------------------------------------------------
__device__ __forceinline__ uint32_t pack_f16x2(float lo, float hi) {
    uint32_t r;
    asm("cvt.rn.f16x2.f32 %0, %1, %2;" : "=r"(r) : "f"(hi), "f"(lo));
    return r;
}

__device__ __forceinline__ void mma_f16(float* c,
                                        uint32_t a0, uint32_t a1, uint32_t a2, uint32_t a3,
                                        uint32_t b0, uint32_t b1) {
    asm volatile("mma.sync.aligned.m16n8k16.row.col.f32.f16.f16.f32 "
                 "{%0,%1,%2,%3}, {%4,%5,%6,%7}, {%8,%9}, {%0,%1,%2,%3};"
                 : "+f"(c[0]), "+f"(c[1]), "+f"(c[2]), "+f"(c[3])
                 : "r"(a0), "r"(a1), "r"(a2), "r"(a3), "r"(b0), "r"(b1));
}

// One channel's 28 MMAs: A fragments (4 x uint4, register-direct) against
// the 14 B pairs read from this channel's shared x window.
__device__ __forceinline__ void mma_channel(float acc[7][4],
                                            uint4 A0, uint4 A1, uint4 A2, uint4 A3,
                                            const uint32_t* __restrict__ sxc,
                                            int bb)
{
    uint32_t P[14];
#pragma unroll
    for (int j = 0; j < 14; ++j) P[j] = sxc[bb + 8 * j];
#pragma unroll
    for (int nb = 0; nb < 7; ++nb)
        mma_f16(acc[nb], A0.x, A0.y, A0.z, A0.w, P[nb],     P[nb + 1]);
#pragma unroll
    for (int nb = 0; nb < 7; ++nb)
        mma_f16(acc[nb], A1.x, A1.y, A1.z, A1.w, P[nb + 2], P[nb + 3]);
#pragma unroll
    for (int nb = 0; nb < 7; ++nb)
        mma_f16(acc[nb], A2.x, A2.y, A2.z, A2.w, P[nb + 4], P[nb + 5]);
#pragma unroll
    for (int nb = 0; nb < 7; ++nb)
        mma_f16(acc[nb], A3.x, A3.y, A3.z, A3.w, P[nb + 6], P[nb + 7]);
}

// load one channel's A fragments (4 x LDG.128) into named uint4 regs
#define LDA(R0, R1, R2, R3, CHN) do {                                          \
        const uint4* ap_ = (const uint4*)(Ae + (size_t)(CHN) * ACH);           \
        R0 = ap_[0]; R1 = ap_[32]; R2 = ap_[64]; R3 = ap_[96];                 \
    } while (0)

// ---------------- kernel 0: W1 fp32 -> per-lane A fragments ---------------
// Output word idx: ((((e*CIN + c)*8 + wp)*4 + kk)*32 + lane)*4 + q
__global__ void k_wconv(const float* __restrict__ W1) {
    int idx  = blockIdx.x * 256 + threadIdx.x;    // [0, NE*CIN*8*4*32)
    int lane = idx & 31;
    int kk   = (idx >> 5) & 3;
    int wp   = (idx >> 7) & 7;
    int c    = (idx >> 10) & 127;
    int e    = idx >> 17;
    int g    = lane >> 2;
    int t4   = lane & 3;
    int olo  = wp * 16 + g;
    int ohi  = olo + 8;
    int tap0 = kk * 16 + 2 * t4;
    const float* Wlo = W1 + ((size_t)(e * COUT + olo) * CIN + c) * KW;
    const float* Whi = W1 + ((size_t)(e * COUT + ohi) * CIN + c) * KW;
    uint4 u;
    u.x = pack_f16x2(Wlo[tap0],     Wlo[tap0 + 1]);
    u.y = pack_f16x2(Whi[tap0],     Whi[tap0 + 1]);
    u.z = pack_f16x2(Wlo[tap0 + 8], Wlo[tap0 + 9]);
    u.w = pack_f16x2(Whi[tap0 + 8], Whi[tap0 + 9]);
    *(uint4*)(g_w1h + (size_t)idx * 4) = u;
}

// ---------------- kernel 1: gate_x = mean over L (warp per row) -----------
__global__ void k_gatex(const float* __restrict__ x) {
    int row  = blockIdx.x * 4 + (threadIdx.x >> 5);   // (b, c) flattened
    int lane = threadIdx.x & 31;
    const float4* xp = (const float4*)(x + (size_t)row * LIN);
    float s = 0.f;
#pragma unroll
    for (int k = 0; k < 8; ++k) {
        float4 v = xp[lane + k * 32];
        s += (v.x + v.y) + (v.z + v.w);
    }
#pragma unroll
    for (int off = 16; off; off >>= 1) s += __shfl_down_sync(0xffffffffu, s, off);
    if (lane == 0) g_gatex[row] = s * (1.0f / (float)LIN);
}

// ---------------- kernel 2: gating, top-k, loss ---------------------------
__device__ __forceinline__ float cv_sq4(const float* w) {
    float mn = 0.25f * (w[0] + w[1] + w[2] + w[3]);
    float s = 0.f;
#pragma unroll
    for (int e = 0; e < 4; ++e) { float d = w[e] - mn; s += d * d; }
    s *= (1.0f / 3.0f);                    // ddof = 1
    return s / (mn * mn + 1e-10f);
}

__global__ void k_gate(const float* __restrict__ noise,
                       const float* __restrict__ w_gate,
                       const float* __restrict__ w_noise,
                       float* __restrict__ out, int loss_idx)
{
    int b = threadIdx.x;                   // 32 threads, one per batch row
    float clean[NE] = {0.f, 0.f, 0.f, 0.f};
    float raw[NE]   = {0.f, 0.f, 0.f, 0.f};
    for (int c = 0; c < CIN; ++c) {
        float gx = g_gatex[b * CIN + c];
#pragma unroll
        for (int e = 0; e < NE; ++e) {
            clean[e] = fmaf(gx, w_gate[c * NE + e],  clean[e]);
            raw[e]   = fmaf(gx, w_noise[c * NE + e], raw[e]);
        }
    }
    float nstd[NE], noisy[NE], sm[NE];
    float m = -1e30f;
#pragma unroll
    for (int e = 0; e < NE; ++e) {
        float r  = raw[e];
        float sp = (r > 20.f) ? r : log1pf(expf(r));   // softplus
        nstd[e]  = sp + 0.01f;                          // NOISE_EPS
        noisy[e] = clean[e] + noise[b * NE + e] * nstd[e];
        m = fmaxf(m, noisy[e]);
    }
    float ssum = 0.f;
#pragma unroll
    for (int e = 0; e < NE; ++e) { sm[e] = expf(noisy[e] - m); ssum += sm[e]; }
    float inv = 1.f / ssum;
#pragma unroll
    for (int e = 0; e < NE; ++e) sm[e] *= inv;

    int   idx[4] = {0, 1, 2, 3};
    float v[4]   = {sm[0], sm[1], sm[2], sm[3]};
#pragma unroll
    for (int a = 0; a < 3; ++a)
#pragma unroll
        for (int q = a + 1; q < 4; ++q)
            if (v[q] > v[a]) {
                float tv = v[a]; v[a] = v[q]; v[q] = tv;
                int   ti = idx[a]; idx[a] = idx[q]; idx[q] = ti;
            }

    float e1 = expf(v[1] - v[0]);
    float gs = 1.f + e1;
    float g0 = 1.f / gs;
    float g1 = e1 / gs;
    g_sel [b * 2 + 0] = idx[0];  g_sel [b * 2 + 1] = idx[1];
    g_selw[b * 2 + 0] = g0;      g_selw[b * 2 + 1] = g1;

    float gates[4] = {0.f, 0.f, 0.f, 0.f};
    gates[idx[0]] = g0;
    gates[idx[1]] = g1;

    float thr_in  = v[2];
    float thr_out = v[1];
    float loadc[4];
#pragma unroll
    for (int e = 0; e < NE; ++e) {
        bool  is_in = noisy[e] > thr_in;
        float thr   = is_in ? thr_in : thr_out;
        float z     = (clean[e] - thr) / nstd[e];
        loadc[e]    = 0.5f * (1.f + erff(z * 0.70710678118654752f));
    }

    float imp[4], ld[4];
#pragma unroll
    for (int e = 0; e < NE; ++e) {
        float a = gates[e], l2 = loadc[e];
        for (int off = 16; off; off >>= 1) {
            a  += __shfl_down_sync(0xffffffffu, a,  off);
            l2 += __shfl_down_sync(0xffffffffu, l2, off);
        }
        imp[e] = a; ld[e] = l2;
    }
    if (b == 0)
        out[loss_idx] = 0.01f * (cv_sq4(imp) + cv_sq4(ld));
}

// ---------------- kernel 3: fp16 tensor-core sparse conv experts ----------
// grid: (NTILES=18, BQ=32) = 576 CTAs, 256 threads (8 warps), 2 CTAs/SM.
// CTA tile: M=128 (Cout) x N=56 (l). Warp w owns m-rows [w*16,+16), full N.
// A register-direct from pre-swizzled g_w1h (R13: L1 68->43%, tensor 72%).
// FOUR channels staged per barrier pair (sxp[4][128], all 256 threads
// participate): barriers drop 2/channel -> 0.5/channel, attacking the
// remaining ~28% tensor-idle which is barrier/staging exposure.
__global__ void __launch_bounds__(256, 2)
k_conv(const float* __restrict__ x,
       const float* __restrict__ b1,
       const float* __restrict__ W2,
       const float* __restrict__ b2,
       float* __restrict__ out)
{
    __shared__ uint32_t sxp[4][128];    // paired x windows for 4 channels, 2KB
    __shared__ float sred[8][4][28];    // epilogue partials
    __shared__ float sz[2][NTILE];
    __shared__ float ysum[2][NTILE];
    __shared__ float sW2[2][COUT];
    __shared__ float sb1[COUT];

    const int b    = blockIdx.y;
    const int l0   = blockIdx.x * NTILE;
    const int tid  = threadIdx.x;
    const int warp = tid >> 5;          // 0..7 = m-group
    const int lane = tid & 31;
    const int g    = lane >> 2;
    const int t4   = lane & 3;
    const int m0   = warp * 16;
    const int rlo  = m0 + g;
    const int rhi  = m0 + g + 8;

    const float* xb = x + (size_t)b * CIN * LIN;
    const int  ch0  = tid >> 7;         // 0 or 1: this thread stages ch0, ch0+2
    const int  pos  = tid & 127;
    const bool pact = (pos < WNDW);
    const int  xl   = l0 + pos;
    const int  bb   = g + 2 * t4;

    if (tid < 2 * NTILE) {
        int t = tid >= NTILE;
        ysum[t][tid - t * NTILE] = 0.f;
    }

    // per-thread A-fragment offset within one (e,c) block: warp/kk/lane
    const size_t a_toff = (((size_t)warp * 4) * 32 + lane) * 4;  // + kk*128

    for (int slot = 0; slot < 2; ++slot) {
        const int   e  = g_sel [b * 2 + slot];
        const float gw = g_selw[b * 2 + slot];
        const uint32_t* Ae = g_w1h + (size_t)e * (CIN * ACH) + a_toff;

        sW2[tid >> 7][tid & 127] = W2[e * 2 * COUT + tid];   // 256 == 2*COUT
        if (tid < COUT) sb1[tid] = b1[e * COUT + tid];

        float acc[7][4];
#pragma unroll
        for (int i = 0; i < 7; ++i)
#pragma unroll
            for (int j = 0; j < 4; ++j) acc[i][j] = 0.f;

        // A fragment double registers + x staging regs (group of 4 channels:
        // this thread stages channels ch0 and ch0+2 at position pos)
        uint4 A_0, A_1, A_2, A_3, B_0, B_1, B_2, B_3;
        float xra0 = 0.f, xrb0 = 0.f, xra1 = 0.f, xrb1 = 0.f;

        // ---- preload: x group 0 (channels 0..3), A channel 0 ----
        if (pact) {
            const float* x0 = xb + (size_t)ch0 * LIN;
            const float* x1 = xb + (size_t)(ch0 + 2) * LIN;
            xra0 = (xl < LIN)     ? x0[xl]     : 0.f;
            xrb0 = (xl + 1 < LIN) ? x0[xl + 1] : 0.f;
            xra1 = (xl < LIN)     ? x1[xl]     : 0.f;
            xrb1 = (xl + 1 < LIN) ? x1[xl + 1] : 0.f;
        }
        LDA(A_0, A_1, A_2, A_3, 0);

        for (int c = 0; c < CIN; c += 4) {
            __syncthreads();            // prior group's P reads done
            if (pact) {
                sxp[ch0][pos]     = pack_f16x2(xra0, xrb0);
                sxp[ch0 + 2][pos] = pack_f16x2(xra1, xrb1);
            }
            __syncthreads();            // staging visible

            // prefetch x for next group (4 channels ahead — ample cover)
            if (c + 4 < CIN && pact) {
                const float* x0 = xb + (size_t)(c + 4 + ch0) * LIN;
                const float* x1 = x0 + 2 * LIN;
                xra0 = (xl < LIN)     ? x0[xl]     : 0.f;
                xrb0 = (xl + 1 < LIN) ? x0[xl + 1] : 0.f;
                xra1 = (xl < LIN)     ? x1[xl]     : 0.f;
                xrb1 = (xl + 1 < LIN) ? x1[xl + 1] : 0.f;
            }

            // 4 channels, alternating A/B register sets, 1-channel prefetch
            LDA(B_0, B_1, B_2, B_3, c + 1);
            mma_channel(acc, A_0, A_1, A_2, A_3, sxp[0], bb);
            LDA(A_0, A_1, A_2, A_3, c + 2);
            mma_channel(acc, B_0, B_1, B_2, B_3, sxp[1], bb);
            LDA(B_0, B_1, B_2, B_3, c + 3);
            mma_channel(acc, A_0, A_1, A_2, A_3, sxp[2], bb);
            if (c + 4 < CIN) LDA(A_0, A_1, A_2, A_3, c + 4);
            mma_channel(acc, B_0, B_1, B_2, B_3, sxp[3], bb);
        }

        // ---- epilogue: bias + relu + W2 partials, reduce over Cout ----
        float b1lo = sb1[rlo], b1hi = sb1[rhi];
        float w2lo0 = sW2[0][rlo], w2hi0 = sW2[0][rhi];
        float w2lo1 = sW2[1][rlo], w2hi1 = sW2[1][rhi];
        float p[28];                    // [nb*4 + r*2 + t], r = col parity
#pragma unroll
        for (int nb = 0; nb < 7; ++nb) {
            float h00 = fmaxf(acc[nb][0] + b1lo, 0.f);   // (rlo, col even)
            float h01 = fmaxf(acc[nb][1] + b1lo, 0.f);   // (rlo, col odd)
            float h10 = fmaxf(acc[nb][2] + b1hi, 0.f);   // (rhi, col even)
            float h11 = fmaxf(acc[nb][3] + b1hi, 0.f);   // (rhi, col odd)
            p[nb * 4 + 0] = fmaf(w2lo0, h00, w2hi0 * h10);
            p[nb * 4 + 1] = fmaf(w2lo1, h00, w2hi1 * h10);
            p[nb * 4 + 2] = fmaf(w2lo0, h01, w2hi0 * h11);
            p[nb * 4 + 3] = fmaf(w2lo1, h01, w2hi1 * h11);
        }
        // reduce over g (8 lanes sharing t4)
#pragma unroll
        for (int j = 0; j < 28; ++j) {
            p[j] += __shfl_down_sync(0xffffffffu, p[j], 16);
            p[j] += __shfl_down_sync(0xffffffffu, p[j], 8);
            p[j] += __shfl_down_sync(0xffffffffu, p[j], 4);
        }
        __syncthreads();                // sred free from prior use
        if (lane < 4) {
#pragma unroll
            for (int j = 0; j < 28; ++j) sred[warp][lane][j] = p[j];
        }
        __syncthreads();

        // z[t][col]: sum the 8 m-warps
        if (tid < 2 * NTILE) {
            int t   = tid >= NTILE;
            int col = tid - t * NTILE;
            int nb  = col >> 3;
            int tt4 = (col >> 1) & 3;
            int r   = col & 1;
            int pj  = nb * 4 + r * 2 + t;
            float z = b2[e * 2 + t];
#pragma unroll
            for (int w8 = 0; w8 < 8; ++w8) z += sred[w8][tt4][pj];
            sz[t][col] = z;
        }
        __syncthreads();

        // 2-way softmax over t, gate-weighted accumulate
        if (tid < NTILE) {
            float z0 = sz[0][tid], z1 = sz[1][tid];
            float mm = fmaxf(z0, z1);
            float a0 = expf(z0 - mm), a1 = expf(z1 - mm);
            float is = 1.f / (a0 + a1);
            ysum[0][tid] += gw * a0 * is;
            ysum[1][tid] += gw * a1 * is;
        }
        __syncthreads();
    }

    if (tid < 2 * NTILE) {
        int t = tid >= NTILE, l = tid - t * NTILE;
        int gl = l0 + l;
        if (gl < LOUT)
            out[((size_t)b * 2 + t) * LOUT + gl] = ysum[t][l];
    }
}

// ---------------- launcher ------------------------------------------------
extern "C" void kernel_launch(void* const* d_in, const int* in_sizes, int n_in,
                              void* d_out, int out_size)
{
    const float* x       = (const float*)d_in[0];
    const float* noise   = (const float*)d_in[1];
    const float* w_gate  = (const float*)d_in[2];
    const float* w_noise = (const float*)d_in[3];
    const float* W1      = (const float*)d_in[4];
    const float* b1      = (const float*)d_in[5];
    const float* W2      = (const float*)d_in[6];
    const float* b2      = (const float*)d_in[7];
    float* out = (float*)d_out;

    k_wconv<<<NE * CIN * 8 * 4 * 32 / 256, 256>>>(W1);
    k_gatex<<<BQ * CIN / 4, 128>>>(x);
    k_gate<<<1, 32>>>(noise, w_gate, w_noise, out, out_size - 1);
    dim3 grid(NTILES, BQ);
    k_conv<<<grid, 256>>>(x, b1, W2, b2, out);
}

// round 15
// speedup vs baseline: 1.3612x; 1.0095x over previous
#include <cuda_runtime.h>
#include <math.h>
#include <stdint.h>

#define BQ    32
#define CIN   128
#define LIN   1024
#define NE    4
#define COUT  128
#define KW    64
#define LOUT  961          // 1024 - 64 + 1
#define NTILE 56
#define NTILES 18          // 18*56 = 1008 >= 961; 576 CTAs, 2/SM -> 1.95 waves
#define WNDW  120          // x window: NTILE + KW - 1 = 119, rounded up
// pre-swizzled A fragments: [e][c][warp(8)][kk(4)][lane(32)][q(4)] uint32
#define ACH   (8 * 4 * 32 * 4)          // words per (e,c) = 4096 (16KB)

// ---------------- scratch (device globals: no allocation allowed) ----------
__device__ float    g_gatex[BQ * CIN];
__device__ int      g_sel [BQ * 2];
__device__ float    g_selw[BQ * 2];
__device__ uint32_t g_w1h[NE * CIN * ACH];   // fragment-ordered f16x2 W1, 8.4MB

// ---------------- helpers -------------------------------------------------
__device__ __forceinline__ uint32_t pack_f16x2(float lo, float hi) {
    uint32_t r;
    asm("cvt.rn.f16x2.f32 %0, %1, %2;" : "=r"(r) : "f"(hi), "f"(lo));
    return r;
}

__device__ __forceinline__ void mma_f16(float* c,
                                        uint32_t a0, uint32_t a1, uint32_t a2, uint32_t a3,
                                        uint32_t b0, uint32_t b1) {
    asm volatile("mma.sync.aligned.m16n8k16.row.col.f32.f16.f16.f32 "
                 "{%0,%1,%2,%3}, {%4,%5,%6,%7}, {%8,%9}, {%0,%1,%2,%3};"
                 : "+f"(c[0]), "+f"(c[1]), "+f"(c[2]), "+f"(c[3])
                 : "r"(a0), "r"(a1), "r"(a2), "r"(a3), "r"(b0), "r"(b1));
}

// One channel's 28 MMAs: A fragments (4 x uint4, register-direct) against
// the 14 B pairs read from this channel's shared x window.
__device__ __forceinline__ void mma_channel(float acc[7][4],
                                            uint4 A0, uint4 A1, uint4 A2, uint4 A3,
                                            const uint32_t* __restrict__ sxc,
                                            int bb)
{
    uint32_t P[14];
#pragma unroll
    for (int j = 0; j < 14; ++j) P[j] = sxc[bb + 8 * j];
#pragma unroll
    for (int nb = 0; nb < 7; ++nb)
        mma_f16(acc[nb], A0.x, A0.y, A0.z, A0.w, P[nb],     P[nb + 1]);
#pragma unroll
    for (int nb = 0; nb < 7; ++nb)
        mma_f16(acc[nb], A1.x, A1.y, A1.z, A1.w, P[nb + 2], P[nb + 3]);
#pragma unroll
    for (int nb = 0; nb < 7; ++nb)
        mma_f16(acc[nb], A2.x, A2.y, A2.z, A2.w, P[nb + 4], P[nb + 5]);
#pragma unroll
    for (int nb = 0; nb < 7; ++nb)
        mma_f16(acc[nb], A3.x, A3.y, A3.z, A3.w, P[nb + 6], P[nb + 7]);
}

// load one channel's A fragments (4 x LDG.128) into named uint4 regs
#define LDA(R0, R1, R2, R3, CHN) do {                                          \
        const uint4* ap_ = (const uint4*)(Ae + (size_t)(CHN) * ACH);           \
        R0 = ap_[0]; R1 = ap_[32]; R2 = ap_[64]; R3 = ap_[96];                 \
    } while (0)

// load x regs for 4-channel group G (this thread: channels 4G+ch0, 4G+ch0+2)
#define LDX(G) do {                                                            \
        if (pact) {                                                            \
            const float* x0_ = xb + (size_t)(4 * (G) + ch0) * LIN;             \
            const float* x1_ = x0_ + 2 * LIN;                                  \
            xra0 = (xl < LIN)     ? x0_[xl]     : 0.f;                         \
            xrb0 = (xl + 1 < LIN) ? x0_[xl + 1] : 0.f;                         \
            xra1 = (xl < LIN)     ? x1_[xl]     : 0.f;                         \
            xrb1 = (xl + 1 < LIN) ? x1_[xl + 1] : 0.f;                         \
        }                                                                      \
    } while (0)

// store staged x regs into buffer BUF (literal 0/1)
#define STX(BUF) do {                                                          \
        if (pact) {                                                            \
            sxp[BUF][ch0][pos]     = pack_f16x2(xra0, xrb0);                   \
            sxp[BUF][ch0 + 2][pos] = pack_f16x2(xra1, xrb1);                   \
        }                                                                      \
    } while (0)

// ---------------- kernel 0: W1 fp32 -> per-lane A fragments ---------------
// Output word idx: ((((e*CIN + c)*8 + wp)*4 + kk)*32 + lane)*4 + q
__global__ void k_wconv(const float* __restrict__ W1) {
    int idx  = blockIdx.x * 256 + threadIdx.x;    // [0, NE*CIN*8*4*32)
    int lane = idx & 31;
    int kk   = (idx >> 5) & 3;
    int wp   = (idx >> 7) & 7;
    int c    = (idx >> 10) & 127;
    int e    = idx >> 17;
    int g    = lane >> 2;
    int t4   = lane & 3;
    int olo  = wp * 16 + g;
    int ohi  = olo + 8;
    int tap0 = kk * 16 + 2 * t4;
    const float* Wlo = W1 + ((size_t)(e * COUT + olo) * CIN + c) * KW;
    const float* Whi = W1 + ((size_t)(e * COUT + ohi) * CIN + c) * KW;
    uint4 u;
    u.x = pack_f16x2(Wlo[tap0],     Wlo[tap0 + 1]);
    u.y = pack_f16x2(Whi[tap0],     Whi[tap0 + 1]);
    u.z = pack_f16x2(Wlo[tap0 + 8], Wlo[tap0 + 9]);
    u.w = pack_f16x2(Whi[tap0 + 8], Whi[tap0 + 9]);
    *(uint4*)(g_w1h + (size_t)idx * 4) = u;
}

// ---------------- kernel 1: gate_x = mean over L (warp per row) -----------
__global__ void k_gatex(const float* __restrict__ x) {
    int row  = blockIdx.x * 4 + (threadIdx.x >> 5);   // (b, c) flattened
    int lane = threadIdx.x & 31;
    const float4* xp = (const float4*)(x + (size_t)row * LIN);
    float s = 0.f;
#pragma unroll
    for (int k = 0; k < 8; ++k) {
        float4 v = xp[lane + k * 32];
        s += (v.x + v.y) + (v.z + v.w);
    }
#pragma unroll
    for (int off = 16; off; off >>= 1) s += __shfl_down_sync(0xffffffffu, s, off);
    if (lane == 0) g_gatex[row] = s * (1.0f / (float)LIN);
}

// ---------------- kernel 2: gating, top-k, loss ---------------------------
__device__ __forceinline__ float cv_sq4(const float* w) {
    float mn = 0.25f * (w[0] + w[1] + w[2] + w[3]);
    float s = 0.f;
#pragma unroll
    for (int e = 0; e < 4; ++e) { float d = w[e] - mn; s += d * d; }
    s *= (1.0f / 3.0f);                    // ddof = 1
    return s / (mn * mn + 1e-10f);
}

__global__ void k_gate(const float* __restrict__ noise,
                       const float* __restrict__ w_gate,
                       const float* __restrict__ w_noise,
                       float* __restrict__ out, int loss_idx)
{
    int b = threadIdx.x;                   // 32 threads, one per batch row
    float clean[NE] = {0.f, 0.f, 0.f, 0.f};
    float raw[NE]   = {0.f, 0.f, 0.f, 0.f};
    for (int c = 0; c < CIN; ++c) {
        float gx = g_gatex[b * CIN + c];
#pragma unroll
        for (int e = 0; e < NE; ++e) {
            clean[e] = fmaf(gx, w_gate[c * NE + e],  clean[e]);
            raw[e]   = fmaf(gx, w_noise[c * NE + e], raw[e]);
        }
    }
    float nstd[NE], noisy[NE], sm[NE];
    float m = -1e30f;
#pragma unroll
    for (int e = 0; e < NE; ++e) {
        float r  = raw[e];
        float sp = (r > 20.f) ? r : log1pf(expf(r));   // softplus
        nstd[e]  = sp + 0.01f;                          // NOISE_EPS
        noisy[e] = clean[e] + noise[b * NE + e] * nstd[e];
        m = fmaxf(m, noisy[e]);
    }
    float ssum = 0.f;
#pragma unroll
    for (int e = 0; e < NE; ++e) { sm[e] = expf(noisy[e] - m); ssum += sm[e]; }
    float inv = 1.f / ssum;
#pragma unroll
    for (int e = 0; e < NE; ++e) sm[e] *= inv;

    int   idx[4] = {0, 1, 2, 3};
    float v[4]   = {sm[0], sm[1], sm[2], sm[3]};
#pragma unroll
    for (int a = 0; a < 3; ++a)
#pragma unroll
        for (int q = a + 1; q < 4; ++q)
            if (v[q] > v[a]) {
                float tv = v[a]; v[a] = v[q]; v[q] = tv;
                int   ti = idx[a]; idx[a] = idx[q]; idx[q] = ti;
            }

    float e1 = expf(v[1] - v[0]);
    float gs = 1.f + e1;
    float g0 = 1.f / gs;
    float g1 = e1 / gs;
    g_sel [b * 2 + 0] = idx[0];  g_sel [b * 2 + 1] = idx[1];
    g_selw[b * 2 + 0] = g0;      g_selw[b * 2 + 1] = g1;

    float gates[4] = {0.f, 0.f, 0.f, 0.f};
    gates[idx[0]] = g0;
    gates[idx[1]] = g1;

    float thr_in  = v[2];
    float thr_out = v[1];
    float loadc[4];
#pragma unroll
    for (int e = 0; e < NE; ++e) {
        bool  is_in = noisy[e] > thr_in;
        float thr   = is_in ? thr_in : thr_out;
        float z     = (clean[e] - thr) / nstd[e];
        loadc[e]    = 0.5f * (1.f + erff(z * 0.70710678118654752f));
    }

    float imp[4], ld[4];
#pragma unroll
    for (int e = 0; e < NE; ++e) {
        float a = gates[e], l2 = loadc[e];
        for (int off = 16; off; off >>= 1) {
            a  += __shfl_down_sync(0xffffffffu, a,  off);
            l2 += __shfl_down_sync(0xffffffffu, l2, off);
        }
        imp[e] = a; ld[e] = l2;
    }
    if (b == 0)
        out[loss_idx] = 0.01f * (cv_sq4(imp) + cv_sq4(ld));
}

// ---------------- kernel 3: fp16 tensor-core sparse conv experts ----------
// grid: (NTILES=18, BQ=32) = 576 CTAs, 256 threads (8 warps), 2 CTAs/SM.
// CTA tile: M=128 (Cout) x N=56 (l). Warp w owns m-rows [w*16,+16), full N.
// A register-direct from pre-swizzled g_w1h (R13). x staged in PING-PONG
// buffers sxp[2][4][128], 4 channels per group, ONE barrier per group
// (0.25/channel): the STS of group G+1 issues before group G's MMAs and is
// drained by the end-of-group barrier — staging fully hidden. Outer loop
// unrolled x2 so all buffer indices are literals (R7 lesson).
__global__ void __launch_bounds__(256, 2)
k_conv(const float* __restrict__ x,
       const float* __restrict__ b1,
       const float* __restrict__ W2,
       const float* __restrict__ b2,
       float* __restrict__ out)
{
    __shared__ uint32_t sxp[2][4][128]; // ping-pong x windows, 4KB
    __shared__ float sred[8][4][28];    // epilogue partials
    __shared__ float sz[2][NTILE];
    __shared__ float ysum[2][NTILE];
    __shared__ float sW2[2][COUT];
    __shared__ float sb1[COUT];

    const int b    = blockIdx.y;
    const int l0   = blockIdx.x * NTILE;
    const int tid  = threadIdx.x;
    const int warp = tid >> 5;          // 0..7 = m-group
    const int lane = tid & 31;
    const int g    = lane >> 2;
    const int t4   = lane & 3;
    const int m0   = warp * 16;
    const int rlo  = m0 + g;
    const int rhi  = m0 + g + 8;

    const float* xb = x + (size_t)b * CIN * LIN;
    const int  ch0  = tid >> 7;         // 0 or 1: stages group-channels ch0, ch0+2
    const int  pos  = tid & 127;
    const bool pact = (pos < WNDW);
    const int  xl   = l0 + pos;
    const int  bb   = g + 2 * t4;

    if (tid < 2 * NTILE) {
        int t = tid >= NTILE;
        ysum[t][tid - t * NTILE] = 0.f;
    }

    // per-thread A-fragment offset within one (e,c) block: warp/kk/lane
    const size_t a_toff = (((size_t)warp * 4) * 32 + lane) * 4;  // + kk*128

    for (int slot = 0; slot < 2; ++slot) {
        const int   e  = g_sel [b * 2 + slot];
        const float gw = g_selw[b * 2 + slot];
        const uint32_t* Ae = g_w1h + (size_t)e * (CIN * ACH) + a_toff;

        sW2[tid >> 7][tid & 127] = W2[e * 2 * COUT + tid];   // 256 == 2*COUT
        if (tid < COUT) sb1[tid] = b1[e * COUT + tid];

        float acc[7][4];
#pragma unroll
        for (int i = 0; i < 7; ++i)
#pragma unroll
            for (int j = 0; j < 4; ++j) acc[i][j] = 0.f;

        uint4 A_0, A_1, A_2, A_3, B_0, B_1, B_2, B_3;
        float xra0 = 0.f, xrb0 = 0.f, xra1 = 0.f, xrb1 = 0.f;

        // ---- pipeline prologue: buf0 <- group0, regs <- group1, A <- ch0 --
        LDX(0);
        STX(0);
        LDX(1);
        LDA(A_0, A_1, A_2, A_3, 0);
        __syncthreads();                // buf0 visible

        // 16 iterations x 8 channels (groups 2k, 2k+1)
        for (int c = 0; c < CIN; c += 8) {
            const int G = c >> 2;       // even group index

            // --- group G (channels c..c+3) from buf0 ---
            STX(1);                     // regs(G+1) -> buf1 (drains at barrier)
            if (c + 8 < CIN) LDX(G + 2);
            LDA(B_0, B_1, B_2, B_3, c + 1);
            mma_channel(acc, A_0, A_1, A_2, A_3, sxp[0][0], bb);
            LDA(A_0, A_1, A_2, A_3, c + 2);
            mma_channel(acc, B_0, B_1, B_2, B_3, sxp[0][1], bb);
            LDA(B_0, B_1, B_2, B_3, c + 3);
            mma_channel(acc, A_0, A_1, A_2, A_3, sxp[0][2], bb);
            LDA(A_0, A_1, A_2, A_3, c + 4);
            mma_channel(acc, B_0, B_1, B_2, B_3, sxp[0][3], bb);
            __syncthreads();            // buf1 visible; buf0 free

            // --- group G+1 (channels c+4..c+7) from buf1 ---
            if (c + 8 < CIN) {
                STX(0);                 // regs(G+2) -> buf0
                if (c + 12 < CIN) LDX(G + 3);
            }
            LDA(B_0, B_1, B_2, B_3, c + 5);
            mma_channel(acc, A_0, A_1, A_2, A_3, sxp[1][0], bb);
            LDA(A_0, A_1, A_2, A_3, c + 6);
            mma_channel(acc, B_0, B_1, B_2, B_3, sxp[1][1], bb);
            LDA(B_0, B_1, B_2, B_3, c + 7);
            mma_channel(acc, A_0, A_1, A_2, A_3, sxp[1][2], bb);
            if (c + 8 < CIN) LDA(A_0, A_1, A_2, A_3, c + 8);
            mma_channel(acc, B_0, B_1, B_2, B_3, sxp[1][3], bb);
            __syncthreads();            // buf0 visible; buf1 free
        }

        // ---- epilogue: bias + relu + W2 partials, reduce over Cout ----
        float b1lo = sb1[rlo], b1hi = sb1[rhi];
        float w2lo0 = sW2[0][rlo], w2hi0 = sW2[0][rhi];
        float w2lo1 = sW2[1][rlo], w2hi1 = sW2[1][rhi];
        float p[28];                    // [nb*4 + r*2 + t], r = col parity
#pragma unroll
        for (int nb = 0; nb < 7; ++nb) {
            float h00 = fmaxf(acc[nb][0] + b1lo, 0.f);   // (rlo, col even)
            float h01 = fmaxf(acc[nb][1] + b1lo, 0.f);   // (rlo, col odd)
            float h10 = fmaxf(acc[nb][2] + b1hi, 0.f);   // (rhi, col even)
            float h11 = fmaxf(acc[nb][3] + b1hi, 0.f);   // (rhi, col odd)
            p[nb * 4 + 0] = fmaf(w2lo0, h00, w2hi0 * h10);
            p[nb * 4 + 1] = fmaf(w2lo1, h00, w2hi1 * h10);
            p[nb * 4 + 2] = fmaf(w2lo0, h01, w2hi0 * h11);
            p[nb * 4 + 3] = fmaf(w2lo1, h01, w2hi1 * h11);
        }
        // reduce over g (8 lanes sharing t4)
#pragma unroll
        for (int j = 0; j < 28; ++j) {
            p[j] += __shfl_down_sync(0xffffffffu, p[j], 16);
            p[j] += __shfl_down_sync(0xffffffffu, p[j], 8);
            p[j] += __shfl_down_sync(0xffffffffu, p[j], 4);
        }
        __syncthreads();                // sred free from prior use
        if (lane < 4) {
#pragma unroll
            for (int j = 0; j < 28; ++j) sred[warp][lane][j] = p[j];
        }
        __syncthreads();

        // z[t][col]: sum the 8 m-warps
        if (tid < 2 * NTILE) {
            int t   = tid >= NTILE;
            int col = tid - t * NTILE;
            int nb  = col >> 3;
            int tt4 = (col >> 1) & 3;
            int r   = col & 1;
            int pj  = nb * 4 + r * 2 + t;
            float z = b2[e * 2 + t];
#pragma unroll
            for (int w8 = 0; w8 < 8; ++w8) z += sred[w8][tt4][pj];
            sz[t][col] = z;
        }
        __syncthreads();

        // 2-way softmax over t, gate-weighted accumulate
        if (tid < NTILE) {
            float z0 = sz[0][tid], z1 = sz[1][tid];
            float mm = fmaxf(z0, z1);
            float a0 = expf(z0 - mm), a1 = expf(z1 - mm);
            float is = 1.f / (a0 + a1);
            ysum[0][tid] += gw * a0 * is;
            ysum[1][tid] += gw * a1 * is;
        }
        __syncthreads();
    }

    if (tid < 2 * NTILE) {
        int t = tid >= NTILE, l = tid - t * NTILE;
        int gl = l0 + l;
        if (gl < LOUT)
            out[((size_t)b * 2 + t) * LOUT + gl] = ysum[t][l];
    }
}

// ---------------- launcher ------------------------------------------------
extern "C" void kernel_launch(void* const* d_in, const int* in_sizes, int n_in,
                              void* d_out, int out_size)
{
    const float* x       = (const float*)d_in[0];
    const float* noise   = (const float*)d_in[1];
    const float* w_gate  = (const float*)d_in[2];
    const float* w_noise = (const float*)d_in[3];
    const float* W1      = (const float*)d_in[4];
    const float* b1      = (const float*)d_in[5];
    const float* W2      = (const float*)d_in[6];
    const float* b2      = (const float*)d_in[7];
    float* out = (float*)d_out;

    k_wconv<<<NE * CIN * 8 * 4 * 32 / 256, 256>>>(W1);
    k_gatex<<<BQ * CIN / 4, 128>>>(x);
    k_gate<<<1, 32>>>(noise, w_gate, w_noise, out, out_size - 1);
    dim3 grid(NTILES, BQ);
    k_conv<<<grid, 256>>>(x, b1, W2, b2, out);
}